// round 16
// baseline (speedup 1.0000x reference)
#include <cuda_runtime.h>
#include <cuda_fp16.h>
#include <cstdint>

#define DD   128
#define TB   64
#define NTHR 256
#define MAXN 100000

// ---- edge smem layout (3 CTAs/SM, 64512 B) --------------------------------
#define E2W    0
#define E2A    17408
#define E2PA   26624
#define E2PB   44032
#define E2TAIL 61440
#define ESMEM_BYTES 64512

// ---- node smem layout (3 CTAs/SM, 74752 B) --------------------------------
#define N2H    0
#define N2W0   17408
#define N2W1   34816
#define N2A0   52224
#define N2A1   61440
#define N2TAIL 70656
#define NSMEM_BYTES 74752

// ---- precompute smem layout (3 CTAs/SM, 53248 B) --------------------------
#define P2W0   0
#define P2W1   17408
#define P2A0   34816
#define P2A1   44032
#define PSMEM_BYTES 53248

// ---- device global scratch ------------------------------------------------
__device__ __half g_aggh[(size_t)MAXN * DD];
__device__ __half g_Paf[(size_t)MAXN * DD];
__device__ __half g_Pbf[(size_t)MAXN * DD];
__device__ float g_colsum[DD];
__device__ float g_sumsq[1];
__device__ float g_mean[DD];
__device__ float g_invrms[1];
__device__ __half g_xf[(size_t)MAXN * DD];
__device__ __half g_eW1f[3 * DD * DD];
__device__ __half g_eW2f[DD * DD];
__device__ __half g_nW1f[2 * DD * DD];
__device__ __half g_nW2f[DD * DD];

// ---- helpers --------------------------------------------------------------
static __device__ __forceinline__ void ldsm4(unsigned r[4], unsigned addr) {
    asm volatile("ldmatrix.sync.aligned.m8n8.x4.shared.b16 {%0,%1,%2,%3}, [%4];\n"
                 : "=r"(r[0]), "=r"(r[1]), "=r"(r[2]), "=r"(r[3]) : "r"(addr));
}
static __device__ __forceinline__ void ldsm4t(unsigned r[4], unsigned addr) {
    asm volatile("ldmatrix.sync.aligned.m8n8.x4.trans.shared.b16 {%0,%1,%2,%3}, [%4];\n"
                 : "=r"(r[0]), "=r"(r[1]), "=r"(r[2]), "=r"(r[3]) : "r"(addr));
}
static __device__ __forceinline__ void mma16816(float d[4], const unsigned a[4],
                                                unsigned b0, unsigned b1) {
    asm volatile("mma.sync.aligned.m16n8k16.row.col.f32.f16.f16.f32 "
                 "{%0,%1,%2,%3}, {%4,%5,%6,%7}, {%8,%9}, {%0,%1,%2,%3};\n"
                 : "+f"(d[0]), "+f"(d[1]), "+f"(d[2]), "+f"(d[3])
                 : "r"(a[0]), "r"(a[1]), "r"(a[2]), "r"(a[3]), "r"(b0), "r"(b1));
}
static __device__ __forceinline__ void cp16(unsigned saddr, const void* g) {
    asm volatile("cp.async.cg.shared.global [%0], [%1], 16;\n" :: "r"(saddr), "l"(g));
}
static __device__ __forceinline__ void cp_commit() { asm volatile("cp.async.commit_group;\n"); }
static __device__ __forceinline__ void cp_wait0()  { asm volatile("cp.async.wait_group 0;\n" ::: "memory"); }
static __device__ __forceinline__ void cp_wait2()  { asm volatile("cp.async.wait_group 2;\n" ::: "memory"); }
static __device__ __forceinline__ void redh4(__half* p, float4 v) {
    __half2 a = __floats2half2_rn(v.x, v.y);
    __half2 b = __floats2half2_rn(v.z, v.w);
    unsigned ua = *(unsigned*)&a, ub = *(unsigned*)&b;
    asm volatile("red.global.add.noftz.v2.f16x2 [%0], {%1,%2};\n"
                 :: "l"(p), "r"(ua), "r"(ub) : "memory");
}

// store float4 as 4 fp16 at [r][c] with one 8B smem store (alignment: STR*2 and c*2 are 8B multiples)
template <int STR>
static __device__ __forceinline__ void h4_store(__half* H, int r, int c, float4 v) {
    __half2 a = __floats2half2_rn(v.x, v.y);
    __half2 b = __floats2half2_rn(v.z, v.w);
    uint2 p = make_uint2(*(unsigned*)&a, *(unsigned*)&b);
    *(uint2*)(H + r * STR + c) = p;
}

// K=64 MMA chunk, 64-row tile: warp tile 32x32, acc[2][4][4]
static __device__ __forceinline__ void mma_chunk64_e(float acc[2][4][4],
                                                     unsigned aB, int astr, int acol0,
                                                     unsigned wB,
                                                     int wm, int wn, int lane) {
    const int ar  = lane & 15;
    const int asl = (lane >> 4) * 8;
#pragma unroll
    for (int ks = 0; ks < 4; ks++) {
        unsigned a[2][4];
        const int acol = acol0 + ks * 16 + asl;
#pragma unroll
        for (int mt = 0; mt < 2; mt++) {
            int arow = wm * 32 + mt * 16 + ar;
            ldsm4(a[mt], aB + (unsigned)((arow * astr + acol) * 2));
        }
        const int brow = ks * 16 + ar;
#pragma unroll
        for (int np = 0; np < 2; np++) {
            int bcol = wn * 32 + np * 16 + asl;
            unsigned b[4];
            ldsm4t(b, wB + (unsigned)((brow * 136 + bcol) * 2));
#pragma unroll
            for (int mt = 0; mt < 2; mt++) {
                mma16816(acc[mt][2 * np],     a[mt], b[0], b[1]);
                mma16816(acc[mt][2 * np + 1], a[mt], b[2], b[3]);
            }
        }
    }
}

// cp.async one 64x128 fp16 weight chunk into wbase (stride 136)
static __device__ __forceinline__ void load_w64(unsigned wbase, const __half* W, int tid) {
#pragma unroll
    for (int i = 0; i < 4; i++) {
        int idx = tid + NTHR * i;
        int r = idx >> 4, u = (idx & 15) * 8;
        cp16(wbase + (unsigned)((r * 136 + u) * 2), W + r * DD + u);
    }
}

// hidden (plain): bias+relu -> fp16 H stride 136; zero acc
static __device__ __forceinline__ void hidden_store_e(float acc[2][4][4], __half* Hh,
                                                      const float* b1S, int wm, int wn, int lane) {
    const int g = lane >> 2, t = lane & 3;
#pragma unroll
    for (int mt = 0; mt < 2; mt++) {
#pragma unroll
        for (int nt = 0; nt < 4; nt++) {
            int col = wn * 32 + nt * 8 + t * 2;
            float bx = b1S[col], by = b1S[col + 1];
            int r0 = wm * 32 + mt * 16 + g;
            *(__half2*)(Hh + r0 * 136 + col) =
                __floats2half2_rn(fmaxf(acc[mt][nt][0] + bx, 0.f), fmaxf(acc[mt][nt][1] + by, 0.f));
            *(__half2*)(Hh + (r0 + 8) * 136 + col) =
                __floats2half2_rn(fmaxf(acc[mt][nt][2] + bx, 0.f), fmaxf(acc[mt][nt][3] + by, 0.f));
            acc[mt][nt][0] = acc[mt][nt][1] = acc[mt][nt][2] = acc[mt][nt][3] = 0.f;
        }
    }
}

// hidden (edge): acc + Pa(smem) + Pb(smem) + b1, relu -> H (aliases E2PA)
static __device__ __forceinline__ void hidden_store_Psm_e(float acc[2][4][4], char* smc,
                                                          const float* b1S,
                                                          int wm, int wn, int lane) {
    const int g = lane >> 2, t = lane & 3;
#pragma unroll
    for (int mt = 0; mt < 2; mt++) {
#pragma unroll
        for (int nt = 0; nt < 4; nt++) {
            int col = wn * 32 + nt * 8 + t * 2;
            float bx = b1S[col], by = b1S[col + 1];
            int r0 = wm * 32 + mt * 16 + g;
            int r1 = r0 + 8;
            unsigned o0 = (unsigned)(r0 * 272 + col * 2);
            unsigned o1 = (unsigned)(r1 * 272 + col * 2);
            float2 pa0 = __half22float2(*(__half2*)(smc + E2PA + o0));
            float2 pb0 = __half22float2(*(__half2*)(smc + E2PB + o0));
            float2 pa1 = __half22float2(*(__half2*)(smc + E2PA + o1));
            float2 pb1 = __half22float2(*(__half2*)(smc + E2PB + o1));
            float h0 = fmaxf(acc[mt][nt][0] + pa0.x + pb0.x + bx, 0.f);
            float h1 = fmaxf(acc[mt][nt][1] + pa0.y + pb0.y + by, 0.f);
            float h2 = fmaxf(acc[mt][nt][2] + pa1.x + pb1.x + bx, 0.f);
            float h3 = fmaxf(acc[mt][nt][3] + pa1.y + pb1.y + by, 0.f);
            *(__half2*)(smc + E2PA + o0) = __floats2half2_rn(h0, h1);
            *(__half2*)(smc + E2PA + o1) = __floats2half2_rn(h2, h3);
            acc[mt][nt][0] = acc[mt][nt][1] = acc[mt][nt][2] = acc[mt][nt][3] = 0.f;
        }
    }
}

// acc + b2 -> Hs fp32 (stride 132) FUSED with LN partial stats:
// per-row partial sum/sumsq from registers, quad-shuffle, smem atomicAdd.
static __device__ __forceinline__ void out_stats_e(const float acc[2][4][4], float* Hs,
                                                   const float* b2S, float* sumS, float* sqS,
                                                   int wm, int wn, int lane) {
    const int g = lane >> 2, t = lane & 3;
#pragma unroll
    for (int mt = 0; mt < 2; mt++) {
        int r0 = wm * 32 + mt * 16 + g;
        float s0 = 0.f, q0 = 0.f, s1 = 0.f, q1 = 0.f;
#pragma unroll
        for (int nt = 0; nt < 4; nt++) {
            int col = wn * 32 + nt * 8 + t * 2;
            float bx = b2S[col], by = b2S[col + 1];
            float v0 = acc[mt][nt][0] + bx, v1 = acc[mt][nt][1] + by;
            float v2 = acc[mt][nt][2] + bx, v3 = acc[mt][nt][3] + by;
            *(float2*)(Hs + r0 * 132 + col)       = make_float2(v0, v1);
            *(float2*)(Hs + (r0 + 8) * 132 + col) = make_float2(v2, v3);
            s0 += v0 + v1; q0 += v0 * v0 + v1 * v1;
            s1 += v2 + v3; q1 += v2 * v2 + v3 * v3;
        }
        // reduce over the quad (t = 0..3 share a row)
#pragma unroll
        for (int o = 1; o <= 2; o <<= 1) {
            s0 += __shfl_xor_sync(0xffffffffu, s0, o);
            q0 += __shfl_xor_sync(0xffffffffu, q0, o);
            s1 += __shfl_xor_sync(0xffffffffu, s1, o);
            q1 += __shfl_xor_sync(0xffffffffu, q1, o);
        }
        if (t == 0) {
            atomicAdd(&sumS[r0], s0);     atomicAdd(&sqS[r0], q0);
            atomicAdd(&sumS[r0 + 8], s1); atomicAdd(&sqS[r0 + 8], q1);
        }
    }
}

// acc -> global fp16 P rows (no bias); zero acc
static __device__ __forceinline__ void store_Ph_e(float acc[2][4][4], __half* P,
                                                  int nb, int Nloc, int wm, int wn, int lane) {
    const int g = lane >> 2, t = lane & 3;
#pragma unroll
    for (int mt = 0; mt < 2; mt++) {
#pragma unroll
        for (int nt = 0; nt < 4; nt++) {
            int col = wn * 32 + nt * 8 + t * 2;
            int r0 = wm * 32 + mt * 16 + g;
            if (r0 < Nloc)
                *(__half2*)(P + (size_t)(nb + r0) * DD + col) =
                    __floats2half2_rn(acc[mt][nt][0], acc[mt][nt][1]);
            if (r0 + 8 < Nloc)
                *(__half2*)(P + (size_t)(nb + r0 + 8) * DD + col) =
                    __floats2half2_rn(acc[mt][nt][2], acc[mt][nt][3]);
            acc[mt][nt][0] = acc[mt][nt][1] = acc[mt][nt][2] = acc[mt][nt][3] = 0.f;
        }
    }
}

// ---- merged prep: x + all weight tensors fp32 -> fp16 ---------------------
__global__ void prep_all(const float* __restrict__ x, int n4x,
                         const float* __restrict__ eW1, const float* __restrict__ eW2,
                         const float* __restrict__ nW1, const float* __restrict__ nW2) {
    const int W1E = 3 * DD * DD / 4, W2E = DD * DD / 4, W3E = 2 * DD * DD / 4;
    int i = blockIdx.x * blockDim.x + threadIdx.x;
    const float* src; __half* dst; int off;
    if (i < n4x) { src = x; dst = g_xf; off = i; }
    else {
        int j = i - n4x;
        if (j < W1E)                       { src = eW1; dst = g_eW1f; off = j; }
        else if (j < W1E + W2E)            { src = eW2; dst = g_eW2f; off = j - W1E; }
        else if (j < W1E + W2E + W3E)      { src = nW1; dst = g_nW1f; off = j - W1E - W2E; }
        else if (j < W1E + 2 * W2E + W3E)  { src = nW2; dst = g_nW2f; off = j - W1E - W2E - W3E; }
        else return;
    }
    float4 v = ((const float4*)src)[off];
    ((__half2*)dst)[2 * off]     = __floats2half2_rn(v.x, v.y);
    ((__half2*)dst)[2 * off + 1] = __floats2half2_rn(v.z, v.w);
}

// ---- precompute P (fp16), 64-row tiles, 3 CTAs/SM -------------------------
__global__ void __launch_bounds__(NTHR, 3)
precompute_P(int Nn)
{
    extern __shared__ char smc[];
    const unsigned sbase = (unsigned)__cvta_generic_to_shared(smc);
    const int tid = threadIdx.x, lane = tid & 31, wid = tid >> 5;
    const int wm = wid & 1, wn = wid >> 1;
    const int nb = blockIdx.x * TB;
    const int Nloc = min(TB, Nn - nb);

    auto loadX = [&](int chunk, unsigned abase) {
        const int c0 = chunk * 64;
#pragma unroll
        for (int i = 0; i < 2; i++) {
            int idx = tid + NTHR * i;
            int r = idx >> 3, u = (idx & 7) * 8;
            if (r < Nloc)
                cp16(sbase + abase + (unsigned)((r * 72 + u) * 2),
                     g_xf + (size_t)(nb + r) * DD + c0 + u);
        }
    };

    float acc[2][4][4];
#pragma unroll
    for (int mt = 0; mt < 2; mt++)
#pragma unroll
        for (int nt = 0; nt < 4; nt++)
#pragma unroll
            for (int q = 0; q < 4; q++) acc[mt][nt][q] = 0.f;

    loadX(0, P2A0);
    loadX(1, P2A1);
    load_w64(sbase + P2W0, g_eW1f, tid);
    cp_commit(); cp_wait0();
    __syncthreads();

    load_w64(sbase + P2W1, g_eW1f + 64 * DD, tid);
    cp_commit();
    mma_chunk64_e(acc, sbase + P2A0, 72, 0, sbase + P2W0, wm, wn, lane);
    cp_wait0(); __syncthreads();

    load_w64(sbase + P2W0, g_eW1f + 128 * DD, tid);
    cp_commit();
    mma_chunk64_e(acc, sbase + P2A1, 72, 0, sbase + P2W1, wm, wn, lane);
    store_Ph_e(acc, g_Paf, nb, Nloc, wm, wn, lane);
    cp_wait0(); __syncthreads();

    load_w64(sbase + P2W1, g_eW1f + 192 * DD, tid);
    cp_commit();
    mma_chunk64_e(acc, sbase + P2A0, 72, 0, sbase + P2W0, wm, wn, lane);
    cp_wait0(); __syncthreads();

    mma_chunk64_e(acc, sbase + P2A1, 72, 0, sbase + P2W1, wm, wn, lane);
    store_Ph_e(acc, g_Pbf, nb, Nloc, wm, wn, lane);
}

// ---------------------------------------------------------------------------
// edge kernel: 64-row tiles, 3 CTAs/SM
__global__ void __launch_bounds__(NTHR, 3)
edge_kernel(const float* __restrict__ ea,
            const int* __restrict__ ei,
            const float* __restrict__ b1, const float* __restrict__ b2,
            const float* __restrict__ gma, const float* __restrict__ bta,
            float* __restrict__ eout, int E)
{
    extern __shared__ char smc[];
    const unsigned sbase = (unsigned)__cvta_generic_to_shared(smc);
    int*   sIdx = (int*)(smc + E2TAIL);              // [0..63]=src, [64..127]=dst
    float* muS  = (float*)(smc + E2TAIL + 512);      // sums, then mu
    float* invS = (float*)(smc + E2TAIL + 768);      // sumsq, then inv
    float* b1S  = (float*)(smc + E2TAIL + 1024);
    float* b2S  = (float*)(smc + E2TAIL + 1536);
    float* gmaS = (float*)(smc + E2TAIL + 2048);
    float* btaS = (float*)(smc + E2TAIL + 2560);
    float* Hs   = (float*)smc;

    const int tid = threadIdx.x, lane = tid & 31, wid = tid >> 5;
    const int wm = wid & 1, wn = wid >> 1;
    const int eb = blockIdx.x * TB;
    const int Eloc = min(TB, E - eb);

    if (tid < 64) {
        sIdx[tid] = (tid < Eloc) ? ei[eb + tid] : 0;
        muS[tid] = 0.f; invS[tid] = 0.f;
    } else if (tid < 128) {
        int t2 = tid - 64;
        sIdx[tid] = (t2 < Eloc) ? ei[E + eb + t2] : 0;
    }
    if (tid < 128) {
        b1S[tid] = b1[tid]; b2S[tid] = b2[tid];
        gmaS[tid] = gma[tid]; btaS[tid] = bta[tid];
    }
    __syncthreads();

    auto loadEA = [&](int chunk) {
        const int c0 = chunk * 64;
        __half* Ah = (__half*)(smc + E2A);
#pragma unroll
        for (int i = 0; i < 4; i++) {
            int idx = tid + NTHR * i;
            int r = idx >> 4, c4 = (idx & 15) * 4;
            if (r < Eloc) {
                float4 v = *(const float4*)(ea + (size_t)(eb + r) * DD + c0 + c4);
                h4_store<72>(Ah, r, c4, v);
            }
        }
    };
    auto loadP = [&](unsigned pbase, const __half* P, int idx0) {
#pragma unroll
        for (int i = 0; i < 4; i++) {
            int idx = tid + NTHR * i;
            int r = idx >> 4, u = (idx & 15) * 8;
            cp16(sbase + pbase + (unsigned)(r * 272 + u * 2),
                 P + (size_t)sIdx[idx0 + r] * DD + u);
        }
    };

    float acc[2][4][4];
#pragma unroll
    for (int mt = 0; mt < 2; mt++)
#pragma unroll
        for (int nt = 0; nt < 4; nt++)
#pragma unroll
            for (int q = 0; q < 4; q++) acc[mt][nt][q] = 0.f;

    // prologue: G0 = W1c chunk0 (ea c0 sync convert), G1 = Pa, G2 = Pb
    load_w64(sbase + E2W, g_eW1f + 256 * DD, tid);
    loadEA(0);
    cp_commit();
    loadP(E2PA, g_Paf, 0);
    cp_commit();
    loadP(E2PB, g_Pbf, 64);
    cp_commit();
    cp_wait2();
    __syncthreads();

    mma_chunk64_e(acc, sbase + E2A, 72, 0, sbase + E2W, wm, wn, lane);
    __syncthreads();

    load_w64(sbase + E2W, g_eW1f + 320 * DD, tid);
    loadEA(1);
    cp_commit();
    cp_wait0();
    __syncthreads();

    mma_chunk64_e(acc, sbase + E2A, 72, 0, sbase + E2W, wm, wn, lane);
    __syncthreads();

    // hidden (+ prefetch GEMM2 W c0 into dead E2W)
    load_w64(sbase + E2W, g_eW2f, tid);
    cp_commit();
    hidden_store_Psm_e(acc, smc, b1S, wm, wn, lane);   // H -> E2PA; reads E2PB
    cp_wait0();
    __syncthreads();

    // prefetch GEMM2 W c1 into dead E2PB, overlapped with GEMM2 c0
    load_w64(sbase + E2PB, g_eW2f + 64 * DD, tid);
    cp_commit();
    mma_chunk64_e(acc, sbase + E2PA, 136, 0, sbase + E2W, wm, wn, lane);
    cp_wait0();
    __syncthreads();
    mma_chunk64_e(acc, sbase + E2PA, 136, 64, sbase + E2PB, wm, wn, lane);
    __syncthreads();

    // epilogue: fused store + stats
    out_stats_e(acc, Hs, b2S, muS, invS, wm, wn, lane);
    __syncthreads();
    if (tid < 64) {
        float mu  = muS[tid] * (1.f / 128.f);
        float var = invS[tid] * (1.f / 128.f) - mu * mu;
        muS[tid]  = mu;
        invS[tid] = rsqrtf(var + 1e-5f);
    }
    __syncthreads();

    const int c4 = 4 * lane;
    float4 g4 = *(const float4*)(gmaS + c4);
    float4 t4 = *(const float4*)(btaS + c4);
#pragma unroll 1
    for (int j = 0; j < 8; j++) {
        int r = wid * 8 + j;
        if (r >= Eloc) continue;
        size_t ge = (size_t)(eb + r);
        float mu = muS[r], inv = invS[r];
        float4 v = *(const float4*)(Hs + r * 132 + c4);
        float4 o;
        o.x = (v.x - mu) * inv * g4.x + t4.x;
        o.y = (v.y - mu) * inv * g4.y + t4.y;
        o.z = (v.z - mu) * inv * g4.z + t4.z;
        o.w = (v.w - mu) * inv * g4.w + t4.w;
        float4 e4 = *(const float4*)(ea + ge * DD + c4);
        e4.x += o.x; e4.y += o.y; e4.z += o.z; e4.w += o.w;
        __stcs((float4*)(eout + ge * DD + c4), e4);
        redh4(&g_aggh[(size_t)sIdx[64 + r] * DD + c4], o);
    }
}

// ---------------------------------------------------------------------------
// node kernel: 64-row tiles, 3 CTAs/SM
__global__ void __launch_bounds__(NTHR, 3)
node_kernel(const float* __restrict__ x,
            const float* __restrict__ b1, const float* __restrict__ b2,
            const float* __restrict__ gma, const float* __restrict__ bta,
            float* __restrict__ xpre, int Nn)
{
    extern __shared__ char smc[];
    const unsigned sbase = (unsigned)__cvta_generic_to_shared(smc);
    float* csum_s = (float*)(smc + N2TAIL);          // 128 col sums + [128]=sumsq
    float* muS  = (float*)(smc + N2TAIL + 1024);
    float* invS = (float*)(smc + N2TAIL + 1280);
    float* b1S  = (float*)(smc + N2TAIL + 1536);
    float* b2S  = (float*)(smc + N2TAIL + 2048);
    float* gmaS = (float*)(smc + N2TAIL + 2560);
    float* btaS = (float*)(smc + N2TAIL + 3072);
    float* Hs   = (float*)smc;

    const int tid = threadIdx.x, lane = tid & 31, wid = tid >> 5;
    const int wm = wid & 1, wn = wid >> 1;
    const int nb = blockIdx.x * TB;
    const int Nloc = min(TB, Nn - nb);

    if (tid < 128) {
        b1S[tid] = b1[tid]; b2S[tid] = b2[tid];
        gmaS[tid] = gma[tid]; btaS[tid] = bta[tid];
    }
    if (tid < 129) csum_s[tid] = 0.f;
    if (tid < 64) { muS[tid] = 0.f; invS[tid] = 0.f; }
    __syncthreads();

    auto loadA = [&](int chunk, unsigned abase) {
        const int c0 = (chunk & 1) * 64;
        const __half* src = (chunk < 2) ? g_xf : g_aggh;
#pragma unroll
        for (int i = 0; i < 2; i++) {
            int idx = tid + NTHR * i;
            int r = idx >> 3, u = (idx & 7) * 8;
            if (r < Nloc)
                cp16(sbase + abase + (unsigned)((r * 72 + u) * 2),
                     src + (size_t)(nb + r) * DD + c0 + u);
        }
    };

    float acc[2][4][4];
#pragma unroll
    for (int mt = 0; mt < 2; mt++)
#pragma unroll
        for (int nt = 0; nt < 4; nt++)
#pragma unroll
            for (int q = 0; q < 4; q++) acc[mt][nt][q] = 0.f;

    load_w64(sbase + N2W0, g_nW1f, tid);
    loadA(0, N2A0);
    cp_commit(); cp_wait0();
    __syncthreads();

    // GEMM1: 4 chunks (x,x,agg,agg); c=3 prefetches W2c0 into dead N2W0
#pragma unroll 1
    for (int c = 0; c < 4; c++) {
        if (c < 3) {
            unsigned wb = ((c + 1) & 1) ? N2W1 : N2W0;
            unsigned ab = ((c + 1) & 1) ? N2A1 : N2A0;
            load_w64(sbase + wb, g_nW1f + (c + 1) * 64 * DD, tid);
            loadA(c + 1, ab);
        } else {
            load_w64(sbase + N2W0, g_nW2f, tid);
        }
        cp_commit();
        unsigned wb = (c & 1) ? N2W1 : N2W0;
        unsigned ab = (c & 1) ? N2A1 : N2A0;
        mma_chunk64_e(acc, sbase + ab, 72, 0, sbase + wb, wm, wn, lane);
        if (c < 3) { cp_wait0(); __syncthreads(); }
    }

    hidden_store_e(acc, (__half*)(smc + N2H), b1S, wm, wn, lane);
    cp_wait0();
    __syncthreads();

    load_w64(sbase + N2W1, g_nW2f + 64 * DD, tid);
    cp_commit();
    mma_chunk64_e(acc, sbase + N2H, 136, 0, sbase + N2W0, wm, wn, lane);
    cp_wait0();
    __syncthreads();
    mma_chunk64_e(acc, sbase + N2H, 136, 64, sbase + N2W1, wm, wn, lane);
    __syncthreads();

    out_stats_e(acc, Hs, b2S, muS, invS, wm, wn, lane);
    __syncthreads();
    if (tid < 64) {
        float mu  = muS[tid] * (1.f / 128.f);
        float var = invS[tid] * (1.f / 128.f) - mu * mu;
        muS[tid]  = mu;
        invS[tid] = rsqrtf(var + 1e-5f);
    }
    __syncthreads();

    // ---- LN + residual + PairNorm partials ----
    const int c4 = 4 * lane;
    float4 g4 = *(const float4*)(gmaS + c4);
    float4 t4 = *(const float4*)(btaS + c4);
    float4 cs = make_float4(0.f, 0.f, 0.f, 0.f);
    float sq_acc = 0.f;
#pragma unroll 1
    for (int j = 0; j < 8; j++) {
        int r = wid * 8 + j;
        if (r >= Nloc) continue;
        size_t gn = (size_t)(nb + r);
        float mu = muS[r], inv = invS[r];
        float4 v = *(const float4*)(Hs + r * 132 + c4);
        float4 xv = *(const float4*)(x + gn * DD + c4);
        float4 xp;
        xp.x = xv.x + (v.x - mu) * inv * g4.x + t4.x;
        xp.y = xv.y + (v.y - mu) * inv * g4.y + t4.y;
        xp.z = xv.z + (v.z - mu) * inv * g4.z + t4.z;
        xp.w = xv.w + (v.w - mu) * inv * g4.w + t4.w;
        *(float4*)(xpre + gn * DD + c4) = xp;
        cs.x += xp.x; cs.y += xp.y; cs.z += xp.z; cs.w += xp.w;
        sq_acc += xp.x * xp.x + xp.y * xp.y + xp.z * xp.z + xp.w * xp.w;
    }
    atomicAdd(&csum_s[c4 + 0], cs.x);
    atomicAdd(&csum_s[c4 + 1], cs.y);
    atomicAdd(&csum_s[c4 + 2], cs.z);
    atomicAdd(&csum_s[c4 + 3], cs.w);
#pragma unroll
    for (int o = 16; o > 0; o >>= 1) sq_acc += __shfl_xor_sync(0xffffffffu, sq_acc, o);
    if (lane == 0) atomicAdd(&csum_s[128], sq_acc);
    __syncthreads();
    if (tid < 128)       atomicAdd(&g_colsum[tid], csum_s[tid]);
    else if (tid == 128) atomicAdd(&g_sumsq[0],    csum_s[128]);
}

// ---------------------------------------------------------------------------
__global__ void rms_kernel(int Nn)
{
    __shared__ float red[128];
    int c = threadIdx.x;
    float m = g_colsum[c] / (float)Nn;
    g_mean[c] = m;
    red[c] = m * m;
    __syncthreads();
    for (int o = 64; o > 0; o >>= 1) {
        if (c < o) red[c] += red[c + o];
        __syncthreads();
    }
    if (c == 0) {
        float ssc = g_sumsq[0] - (float)Nn * red[0];
        float rms = sqrtf(ssc / (float)Nn) + 1e-8f;
        g_invrms[0] = 1.0f / rms;
    }
}

__global__ void finalize_kernel(float* __restrict__ xout, int n4)
{
    int base = blockIdx.x * (blockDim.x * 4) + threadIdx.x;
    float inv = g_invrms[0];
#pragma unroll
    for (int k = 0; k < 4; k++) {
        int i = base + k * 256;
        if (i < n4) {
            float4 v = ((const float4*)xout)[i];
            int c = (i * 4) & 127;
            v.x = (v.x - g_mean[c])     * inv;
            v.y = (v.y - g_mean[c + 1]) * inv;
            v.z = (v.z - g_mean[c + 2]) * inv;
            v.w = (v.w - g_mean[c + 3]) * inv;
            ((float4*)xout)[i] = v;
        }
    }
}

// ---------------------------------------------------------------------------
extern "C" void kernel_launch(void* const* d_in, const int* in_sizes, int n_in,
                              void* d_out, int out_size)
{
    const float* x   = (const float*)d_in[0];
    const float* ea  = (const float*)d_in[1];
    const int*   ei  = (const int*)d_in[2];      // int32 (JAX x64 disabled)
    const float* eW1 = (const float*)d_in[3];
    const float* eb1 = (const float*)d_in[4];
    const float* eW2 = (const float*)d_in[5];
    const float* eb2 = (const float*)d_in[6];
    const float* eg  = (const float*)d_in[7];
    const float* ebt = (const float*)d_in[8];
    const float* nW1 = (const float*)d_in[9];
    const float* nb1 = (const float*)d_in[10];
    const float* nW2 = (const float*)d_in[11];
    const float* nb2 = (const float*)d_in[12];
    const float* ng  = (const float*)d_in[13];
    const float* nbt = (const float*)d_in[14];

    const int Nn = in_sizes[0] / DD;
    const int E  = in_sizes[1] / DD;

    float* xout = (float*)d_out;
    float* eout = xout + (size_t)Nn * DD;

    cudaFuncSetAttribute(edge_kernel,  cudaFuncAttributeMaxDynamicSharedMemorySize, ESMEM_BYTES);
    cudaFuncSetAttribute(node_kernel,  cudaFuncAttributeMaxDynamicSharedMemorySize, NSMEM_BYTES);
    cudaFuncSetAttribute(precompute_P, cudaFuncAttributeMaxDynamicSharedMemorySize, PSMEM_BYTES);

    void *aggp, *csp, *sqp;
    cudaGetSymbolAddress(&aggp, g_aggh);
    cudaGetSymbolAddress(&csp,  g_colsum);
    cudaGetSymbolAddress(&sqp,  g_sumsq);

    cudaMemsetAsync(aggp, 0, (size_t)Nn * DD * sizeof(__half));
    cudaMemsetAsync(csp,  0, DD * sizeof(float));
    cudaMemsetAsync(sqp,  0, sizeof(float));

    {
        int n4x  = Nn * DD / 4;
        int wtot = 7 * DD * DD / 4;
        prep_all<<<(n4x + wtot + 255) / 256, 256>>>(x, n4x, eW1, eW2, nW1, nW2);
    }

    const int pblocks = (Nn + TB - 1) / TB;
    precompute_P<<<pblocks, NTHR, PSMEM_BYTES>>>(Nn);

    const int eblocks = (E + TB - 1) / TB;
    edge_kernel<<<eblocks, NTHR, ESMEM_BYTES>>>(ea, ei, eb1, eb2, eg, ebt, eout, E);

    const int nblocks = (Nn + TB - 1) / TB;
    node_kernel<<<nblocks, NTHR, NSMEM_BYTES>>>(x, nb1, nb2, ng, nbt, xout, Nn);

    rms_kernel<<<1, 128>>>(Nn);

    const int n4 = Nn * DD / 4;
    finalize_kernel<<<(n4 + 1023) / 1024, 256>>>(xout, n4);
}

// round 17
// speedup vs baseline: 1.4803x; 1.4803x over previous
#include <cuda_runtime.h>
#include <cuda_fp16.h>
#include <cstdint>

#define DD   128
#define TB   64
#define NTHR 256
#define MAXN 100000

// ---- edge smem layout (3 CTAs/SM, 64512 B) --------------------------------
#define E2W    0
#define E2A    17408
#define E2PA   26624
#define E2PB   44032
#define E2TAIL 61440
#define ESMEM_BYTES 64512

// ---- node smem layout (3 CTAs/SM, 74752 B) --------------------------------
#define N2H    0
#define N2W0   17408
#define N2W1   34816
#define N2A0   52224
#define N2A1   61440
#define N2TAIL 70656
#define NSMEM_BYTES 74752

// ---- precompute smem layout (3 CTAs/SM, 53248 B) --------------------------
#define P2W0   0
#define P2W1   17408
#define P2A0   34816
#define P2A1   44032
#define PSMEM_BYTES 53248

// ---- device global scratch ------------------------------------------------
__device__ __half g_aggh[(size_t)MAXN * DD];
__device__ __half g_Paf[(size_t)MAXN * DD];
__device__ __half g_Pbf[(size_t)MAXN * DD];
__device__ float g_colsum[DD];
__device__ float g_sumsq[1];
__device__ float g_mean[DD];
__device__ float g_invrms[1];
__device__ __half g_xf[(size_t)MAXN * DD];
__device__ __half g_eW1f[3 * DD * DD];
__device__ __half g_eW2f[DD * DD];
__device__ __half g_nW1f[2 * DD * DD];
__device__ __half g_nW2f[DD * DD];

// ---- helpers --------------------------------------------------------------
static __device__ __forceinline__ void warp_red2(float& a, float& b) {
#pragma unroll
    for (int o = 16; o > 0; o >>= 1) {
        a += __shfl_xor_sync(0xffffffffu, a, o);
        b += __shfl_xor_sync(0xffffffffu, b, o);
    }
}
static __device__ __forceinline__ void ldsm4(unsigned r[4], unsigned addr) {
    asm volatile("ldmatrix.sync.aligned.m8n8.x4.shared.b16 {%0,%1,%2,%3}, [%4];\n"
                 : "=r"(r[0]), "=r"(r[1]), "=r"(r[2]), "=r"(r[3]) : "r"(addr));
}
static __device__ __forceinline__ void ldsm4t(unsigned r[4], unsigned addr) {
    asm volatile("ldmatrix.sync.aligned.m8n8.x4.trans.shared.b16 {%0,%1,%2,%3}, [%4];\n"
                 : "=r"(r[0]), "=r"(r[1]), "=r"(r[2]), "=r"(r[3]) : "r"(addr));
}
static __device__ __forceinline__ void mma16816(float d[4], const unsigned a[4],
                                                unsigned b0, unsigned b1) {
    asm volatile("mma.sync.aligned.m16n8k16.row.col.f32.f16.f16.f32 "
                 "{%0,%1,%2,%3}, {%4,%5,%6,%7}, {%8,%9}, {%0,%1,%2,%3};\n"
                 : "+f"(d[0]), "+f"(d[1]), "+f"(d[2]), "+f"(d[3])
                 : "r"(a[0]), "r"(a[1]), "r"(a[2]), "r"(a[3]), "r"(b0), "r"(b1));
}
static __device__ __forceinline__ void cp16(unsigned saddr, const void* g) {
    asm volatile("cp.async.cg.shared.global [%0], [%1], 16;\n" :: "r"(saddr), "l"(g));
}
static __device__ __forceinline__ void cp_commit() { asm volatile("cp.async.commit_group;\n"); }
static __device__ __forceinline__ void cp_wait0()  { asm volatile("cp.async.wait_group 0;\n" ::: "memory"); }
static __device__ __forceinline__ void cp_wait2()  { asm volatile("cp.async.wait_group 2;\n" ::: "memory"); }
static __device__ __forceinline__ void redh4(__half* p, float4 v) {
    __half2 a = __floats2half2_rn(v.x, v.y);
    __half2 b = __floats2half2_rn(v.z, v.w);
    unsigned ua = *(unsigned*)&a, ub = *(unsigned*)&b;
    asm volatile("red.global.add.noftz.v2.f16x2 [%0], {%1,%2};\n"
                 :: "l"(p), "r"(ua), "r"(ub) : "memory");
}

template <int STR>
static __device__ __forceinline__ void h4_store(__half* H, int r, int c, float4 v) {
    __half2 a = __floats2half2_rn(v.x, v.y);
    __half2 b = __floats2half2_rn(v.z, v.w);
    *(__half2*)(H + r * STR + c)     = a;
    *(__half2*)(H + r * STR + c + 2) = b;
}

// K=64 MMA chunk, 64-row tile: warp tile 32x32, acc[2][4][4]
static __device__ __forceinline__ void mma_chunk64_e(float acc[2][4][4],
                                                     unsigned aB, int astr, int acol0,
                                                     unsigned wB,
                                                     int wm, int wn, int lane) {
    const int ar  = lane & 15;
    const int asl = (lane >> 4) * 8;
#pragma unroll
    for (int ks = 0; ks < 4; ks++) {
        unsigned a[2][4];
        const int acol = acol0 + ks * 16 + asl;
#pragma unroll
        for (int mt = 0; mt < 2; mt++) {
            int arow = wm * 32 + mt * 16 + ar;
            ldsm4(a[mt], aB + (unsigned)((arow * astr + acol) * 2));
        }
        const int brow = ks * 16 + ar;
#pragma unroll
        for (int np = 0; np < 2; np++) {
            int bcol = wn * 32 + np * 16 + asl;
            unsigned b[4];
            ldsm4t(b, wB + (unsigned)((brow * 136 + bcol) * 2));
#pragma unroll
            for (int mt = 0; mt < 2; mt++) {
                mma16816(acc[mt][2 * np],     a[mt], b[0], b[1]);
                mma16816(acc[mt][2 * np + 1], a[mt], b[2], b[3]);
            }
        }
    }
}

// cp.async one 64x128 fp16 weight chunk into wbase (stride 136)
static __device__ __forceinline__ void load_w64(unsigned wbase, const __half* W, int tid) {
#pragma unroll
    for (int i = 0; i < 4; i++) {
        int idx = tid + NTHR * i;
        int r = idx >> 4, u = (idx & 15) * 8;
        cp16(wbase + (unsigned)((r * 136 + u) * 2), W + r * DD + u);
    }
}

// hidden (plain): bias+relu -> fp16 H stride 136; zero acc
static __device__ __forceinline__ void hidden_store_e(float acc[2][4][4], __half* Hh,
                                                      const float* b1S, int wm, int wn, int lane) {
    const int g = lane >> 2, t = lane & 3;
#pragma unroll
    for (int mt = 0; mt < 2; mt++) {
#pragma unroll
        for (int nt = 0; nt < 4; nt++) {
            int col = wn * 32 + nt * 8 + t * 2;
            float bx = b1S[col], by = b1S[col + 1];
            int r0 = wm * 32 + mt * 16 + g;
            *(__half2*)(Hh + r0 * 136 + col) =
                __floats2half2_rn(fmaxf(acc[mt][nt][0] + bx, 0.f), fmaxf(acc[mt][nt][1] + by, 0.f));
            *(__half2*)(Hh + (r0 + 8) * 136 + col) =
                __floats2half2_rn(fmaxf(acc[mt][nt][2] + bx, 0.f), fmaxf(acc[mt][nt][3] + by, 0.f));
            acc[mt][nt][0] = acc[mt][nt][1] = acc[mt][nt][2] = acc[mt][nt][3] = 0.f;
        }
    }
}

// hidden (edge): acc + Pa(smem) + Pb(smem) + b1, relu -> H (aliases E2PA)
static __device__ __forceinline__ void hidden_store_Psm_e(float acc[2][4][4], char* smc,
                                                          const float* b1S,
                                                          int wm, int wn, int lane) {
    const int g = lane >> 2, t = lane & 3;
#pragma unroll
    for (int mt = 0; mt < 2; mt++) {
#pragma unroll
        for (int nt = 0; nt < 4; nt++) {
            int col = wn * 32 + nt * 8 + t * 2;
            float bx = b1S[col], by = b1S[col + 1];
            int r0 = wm * 32 + mt * 16 + g;
            int r1 = r0 + 8;
            unsigned o0 = (unsigned)(r0 * 272 + col * 2);
            unsigned o1 = (unsigned)(r1 * 272 + col * 2);
            float2 pa0 = __half22float2(*(__half2*)(smc + E2PA + o0));
            float2 pb0 = __half22float2(*(__half2*)(smc + E2PB + o0));
            float2 pa1 = __half22float2(*(__half2*)(smc + E2PA + o1));
            float2 pb1 = __half22float2(*(__half2*)(smc + E2PB + o1));
            float h0 = fmaxf(acc[mt][nt][0] + pa0.x + pb0.x + bx, 0.f);
            float h1 = fmaxf(acc[mt][nt][1] + pa0.y + pb0.y + by, 0.f);
            float h2 = fmaxf(acc[mt][nt][2] + pa1.x + pb1.x + bx, 0.f);
            float h3 = fmaxf(acc[mt][nt][3] + pa1.y + pb1.y + by, 0.f);
            *(__half2*)(smc + E2PA + o0) = __floats2half2_rn(h0, h1);
            *(__half2*)(smc + E2PA + o1) = __floats2half2_rn(h2, h3);
            acc[mt][nt][0] = acc[mt][nt][1] = acc[mt][nt][2] = acc[mt][nt][3] = 0.f;
        }
    }
}

// acc + b2 -> Hs fp32 (stride 132), 64-row tile
static __device__ __forceinline__ void out_store_e(const float acc[2][4][4], float* Hs,
                                                   const float* b2S, int wm, int wn, int lane) {
    const int g = lane >> 2, t = lane & 3;
#pragma unroll
    for (int mt = 0; mt < 2; mt++) {
#pragma unroll
        for (int nt = 0; nt < 4; nt++) {
            int col = wn * 32 + nt * 8 + t * 2;
            float bx = b2S[col], by = b2S[col + 1];
            int r0 = wm * 32 + mt * 16 + g;
            *(float2*)(Hs + r0 * 132 + col)       = make_float2(acc[mt][nt][0] + bx, acc[mt][nt][1] + by);
            *(float2*)(Hs + (r0 + 8) * 132 + col) = make_float2(acc[mt][nt][2] + bx, acc[mt][nt][3] + by);
        }
    }
}

// acc -> global fp16 P rows (no bias); zero acc (64-row tile)
static __device__ __forceinline__ void store_Ph_e(float acc[2][4][4], __half* P,
                                                  int nb, int Nloc, int wm, int wn, int lane) {
    const int g = lane >> 2, t = lane & 3;
#pragma unroll
    for (int mt = 0; mt < 2; mt++) {
#pragma unroll
        for (int nt = 0; nt < 4; nt++) {
            int col = wn * 32 + nt * 8 + t * 2;
            int r0 = wm * 32 + mt * 16 + g;
            if (r0 < Nloc)
                *(__half2*)(P + (size_t)(nb + r0) * DD + col) =
                    __floats2half2_rn(acc[mt][nt][0], acc[mt][nt][1]);
            if (r0 + 8 < Nloc)
                *(__half2*)(P + (size_t)(nb + r0 + 8) * DD + col) =
                    __floats2half2_rn(acc[mt][nt][2], acc[mt][nt][3]);
            acc[mt][nt][0] = acc[mt][nt][1] = acc[mt][nt][2] = acc[mt][nt][3] = 0.f;
        }
    }
}

// per-row LN stats for 64-row tile (8 rows/warp)
static __device__ __forceinline__ void stats_rows64(const float* Hs, float* muS, float* invS,
                                                    int wid, int lane) {
#pragma unroll 1
    for (int j = 0; j < 8; j++) {
        int r = wid * 8 + j;
        float s = 0.f, sq = 0.f;
#pragma unroll
        for (int q = 0; q < 4; q++) {
            float v = Hs[r * 132 + lane + 32 * q];
            s += v; sq += v * v;
        }
        warp_red2(s, sq);
        if (lane == 0) {
            float mu = s * (1.f / 128.f);
            muS[r]  = mu;
            invS[r] = rsqrtf(sq * (1.f / 128.f) - mu * mu + 1e-5f);
        }
    }
}

// ---- merged prep: x + all weight tensors fp32 -> fp16 (one launch) --------
__global__ void prep_all(const float* __restrict__ x, int n4x,
                         const float* __restrict__ eW1, const float* __restrict__ eW2,
                         const float* __restrict__ nW1, const float* __restrict__ nW2) {
    const int W1E = 3 * DD * DD / 4, W2E = DD * DD / 4, W3E = 2 * DD * DD / 4;
    int i = blockIdx.x * blockDim.x + threadIdx.x;
    const float* src; __half* dst; int off;
    if (i < n4x) { src = x; dst = g_xf; off = i; }
    else {
        int j = i - n4x;
        if (j < W1E)                       { src = eW1; dst = g_eW1f; off = j; }
        else if (j < W1E + W2E)            { src = eW2; dst = g_eW2f; off = j - W1E; }
        else if (j < W1E + W2E + W3E)      { src = nW1; dst = g_nW1f; off = j - W1E - W2E; }
        else if (j < W1E + 2 * W2E + W3E)  { src = nW2; dst = g_nW2f; off = j - W1E - W2E - W3E; }
        else return;
    }
    float4 v = ((const float4*)src)[off];
    ((__half2*)dst)[2 * off]     = __floats2half2_rn(v.x, v.y);
    ((__half2*)dst)[2 * off + 1] = __floats2half2_rn(v.z, v.w);
}

// ---- precompute P (fp16), 64-row tiles, 3 CTAs/SM -------------------------
__global__ void __launch_bounds__(NTHR, 3)
precompute_P(int Nn)
{
    extern __shared__ char smc[];
    const unsigned sbase = (unsigned)__cvta_generic_to_shared(smc);
    const int tid = threadIdx.x, lane = tid & 31, wid = tid >> 5;
    const int wm = wid & 1, wn = wid >> 1;
    const int nb = blockIdx.x * TB;
    const int Nloc = min(TB, Nn - nb);

    auto loadX = [&](int chunk, unsigned abase) {
        const int c0 = chunk * 64;
#pragma unroll
        for (int i = 0; i < 2; i++) {
            int idx = tid + NTHR * i;
            int r = idx >> 3, u = (idx & 7) * 8;
            if (r < Nloc)
                cp16(sbase + abase + (unsigned)((r * 72 + u) * 2),
                     g_xf + (size_t)(nb + r) * DD + c0 + u);
        }
    };

    float acc[2][4][4];
#pragma unroll
    for (int mt = 0; mt < 2; mt++)
#pragma unroll
        for (int nt = 0; nt < 4; nt++)
#pragma unroll
            for (int q = 0; q < 4; q++) acc[mt][nt][q] = 0.f;

    loadX(0, P2A0);
    loadX(1, P2A1);
    load_w64(sbase + P2W0, g_eW1f, tid);
    cp_commit(); cp_wait0();
    __syncthreads();

    load_w64(sbase + P2W1, g_eW1f + 64 * DD, tid);
    cp_commit();
    mma_chunk64_e(acc, sbase + P2A0, 72, 0, sbase + P2W0, wm, wn, lane);
    cp_wait0(); __syncthreads();

    load_w64(sbase + P2W0, g_eW1f + 128 * DD, tid);
    cp_commit();
    mma_chunk64_e(acc, sbase + P2A1, 72, 0, sbase + P2W1, wm, wn, lane);
    store_Ph_e(acc, g_Paf, nb, Nloc, wm, wn, lane);
    cp_wait0(); __syncthreads();

    load_w64(sbase + P2W1, g_eW1f + 192 * DD, tid);
    cp_commit();
    mma_chunk64_e(acc, sbase + P2A0, 72, 0, sbase + P2W0, wm, wn, lane);
    cp_wait0(); __syncthreads();

    mma_chunk64_e(acc, sbase + P2A1, 72, 0, sbase + P2W1, wm, wn, lane);
    store_Ph_e(acc, g_Pbf, nb, Nloc, wm, wn, lane);
}

// ---------------------------------------------------------------------------
// edge kernel: 64-row tiles, 3 CTAs/SM
__global__ void __launch_bounds__(NTHR, 3)
edge_kernel(const float* __restrict__ ea,
            const int* __restrict__ ei,
            const float* __restrict__ b1, const float* __restrict__ b2,
            const float* __restrict__ gma, const float* __restrict__ bta,
            float* __restrict__ eout, int E)
{
    extern __shared__ char smc[];
    const unsigned sbase = (unsigned)__cvta_generic_to_shared(smc);
    int*   sIdx = (int*)(smc + E2TAIL);              // [0..63]=src, [64..127]=dst
    float* muS  = (float*)(smc + E2TAIL + 512);
    float* invS = (float*)(smc + E2TAIL + 768);
    float* b1S  = (float*)(smc + E2TAIL + 1024);
    float* b2S  = (float*)(smc + E2TAIL + 1536);
    float* gmaS = (float*)(smc + E2TAIL + 2048);
    float* btaS = (float*)(smc + E2TAIL + 2560);
    float* Hs   = (float*)smc;

    const int tid = threadIdx.x, lane = tid & 31, wid = tid >> 5;
    const int wm = wid & 1, wn = wid >> 1;
    const int eb = blockIdx.x * TB;
    const int Eloc = min(TB, E - eb);

    if (tid < 64)       sIdx[tid] = (tid < Eloc) ? ei[eb + tid] : 0;
    else if (tid < 128) { int t2 = tid - 64; sIdx[tid] = (t2 < Eloc) ? ei[E + eb + t2] : 0; }
    if (tid < 128) {
        b1S[tid] = b1[tid]; b2S[tid] = b2[tid];
        gmaS[tid] = gma[tid]; btaS[tid] = bta[tid];
    }
    __syncthreads();

    auto loadEA = [&](int chunk) {
        const int c0 = chunk * 64;
        __half* Ah = (__half*)(smc + E2A);
#pragma unroll
        for (int i = 0; i < 4; i++) {
            int idx = tid + NTHR * i;
            int r = idx >> 4, c4 = (idx & 15) * 4;
            if (r < Eloc) {
                float4 v = *(const float4*)(ea + (size_t)(eb + r) * DD + c0 + c4);
                h4_store<72>(Ah, r, c4, v);
            }
        }
    };
    auto loadP = [&](unsigned pbase, const __half* P, int idx0) {
#pragma unroll
        for (int i = 0; i < 4; i++) {
            int idx = tid + NTHR * i;
            int r = idx >> 4, u = (idx & 15) * 8;
            cp16(sbase + pbase + (unsigned)(r * 272 + u * 2),
                 P + (size_t)sIdx[idx0 + r] * DD + u);
        }
    };

    float acc[2][4][4];
#pragma unroll
    for (int mt = 0; mt < 2; mt++)
#pragma unroll
        for (int nt = 0; nt < 4; nt++)
#pragma unroll
            for (int q = 0; q < 4; q++) acc[mt][nt][q] = 0.f;

    // prologue: G0 = W1c chunk0 (ea c0 sync convert), G1 = Pa, G2 = Pb
    load_w64(sbase + E2W, g_eW1f + 256 * DD, tid);
    loadEA(0);
    cp_commit();
    loadP(E2PA, g_Paf, 0);
    cp_commit();
    loadP(E2PB, g_Pbf, 64);
    cp_commit();
    cp_wait2();
    __syncthreads();

    // GEMM1c chunk 0
    mma_chunk64_e(acc, sbase + E2A, 72, 0, sbase + E2W, wm, wn, lane);
    __syncthreads();

    load_w64(sbase + E2W, g_eW1f + 320 * DD, tid);
    loadEA(1);
    cp_commit();
    cp_wait0();
    __syncthreads();

    // GEMM1c chunk 1
    mma_chunk64_e(acc, sbase + E2A, 72, 0, sbase + E2W, wm, wn, lane);
    __syncthreads();

    // hidden (+ prefetch GEMM2 W c0 into dead E2W)
    load_w64(sbase + E2W, g_eW2f, tid);
    cp_commit();
    hidden_store_Psm_e(acc, smc, b1S, wm, wn, lane);   // H -> E2PA; reads E2PB
    cp_wait0();
    __syncthreads();                                   // all EPB reads done

    // prefetch GEMM2 W c1 into dead E2PB, overlapped with GEMM2 c0
    load_w64(sbase + E2PB, g_eW2f + 64 * DD, tid);
    cp_commit();
    mma_chunk64_e(acc, sbase + E2PA, 136, 0, sbase + E2W, wm, wn, lane);
    cp_wait0();
    __syncthreads();
    mma_chunk64_e(acc, sbase + E2PA, 136, 64, sbase + E2PB, wm, wn, lane);
    __syncthreads();

    // epilogue
    out_store_e(acc, Hs, b2S, wm, wn, lane);
    __syncthreads();
    stats_rows64(Hs, muS, invS, wid, lane);
    __syncthreads();

    const int c4 = 4 * lane;
    float4 g4 = *(const float4*)(gmaS + c4);
    float4 t4 = *(const float4*)(btaS + c4);
#pragma unroll 1
    for (int j = 0; j < 8; j++) {
        int r = wid * 8 + j;
        if (r >= Eloc) continue;
        size_t ge = (size_t)(eb + r);
        float mu = muS[r], inv = invS[r];
        float4 v = *(const float4*)(Hs + r * 132 + c4);
        float4 o;
        o.x = (v.x - mu) * inv * g4.x + t4.x;
        o.y = (v.y - mu) * inv * g4.y + t4.y;
        o.z = (v.z - mu) * inv * g4.z + t4.z;
        o.w = (v.w - mu) * inv * g4.w + t4.w;
        float4 e4 = *(const float4*)(ea + ge * DD + c4);
        e4.x += o.x; e4.y += o.y; e4.z += o.z; e4.w += o.w;
        __stcs((float4*)(eout + ge * DD + c4), e4);
        redh4(&g_aggh[(size_t)sIdx[64 + r] * DD + c4], o);
    }
}

// ---------------------------------------------------------------------------
// node kernel: 64-row tiles, 3 CTAs/SM
__global__ void __launch_bounds__(NTHR, 3)
node_kernel(const float* __restrict__ x,
            const float* __restrict__ b1, const float* __restrict__ b2,
            const float* __restrict__ gma, const float* __restrict__ bta,
            float* __restrict__ xpre, int Nn)
{
    extern __shared__ char smc[];
    const unsigned sbase = (unsigned)__cvta_generic_to_shared(smc);
    float* csum_s = (float*)(smc + N2TAIL);          // 128 col sums + [128]=sumsq
    float* muS  = (float*)(smc + N2TAIL + 1024);
    float* invS = (float*)(smc + N2TAIL + 1280);
    float* b1S  = (float*)(smc + N2TAIL + 1536);
    float* b2S  = (float*)(smc + N2TAIL + 2048);
    float* gmaS = (float*)(smc + N2TAIL + 2560);
    float* btaS = (float*)(smc + N2TAIL + 3072);
    float* Hs   = (float*)smc;

    const int tid = threadIdx.x, lane = tid & 31, wid = tid >> 5;
    const int wm = wid & 1, wn = wid >> 1;
    const int nb = blockIdx.x * TB;
    const int Nloc = min(TB, Nn - nb);

    if (tid < 128) {
        b1S[tid] = b1[tid]; b2S[tid] = b2[tid];
        gmaS[tid] = gma[tid]; btaS[tid] = bta[tid];
    }
    if (tid < 129) csum_s[tid] = 0.f;
    __syncthreads();

    auto loadA = [&](int chunk, unsigned abase) {
        const int c0 = (chunk & 1) * 64;
        const __half* src = (chunk < 2) ? g_xf : g_aggh;
#pragma unroll
        for (int i = 0; i < 2; i++) {
            int idx = tid + NTHR * i;
            int r = idx >> 3, u = (idx & 7) * 8;
            if (r < Nloc)
                cp16(sbase + abase + (unsigned)((r * 72 + u) * 2),
                     src + (size_t)(nb + r) * DD + c0 + u);
        }
    };

    float acc[2][4][4];
#pragma unroll
    for (int mt = 0; mt < 2; mt++)
#pragma unroll
        for (int nt = 0; nt < 4; nt++)
#pragma unroll
            for (int q = 0; q < 4; q++) acc[mt][nt][q] = 0.f;

    load_w64(sbase + N2W0, g_nW1f, tid);
    loadA(0, N2A0);
    cp_commit(); cp_wait0();
    __syncthreads();

    // GEMM1: 4 chunks (x,x,agg,agg); c=3 prefetches W2c0 into dead N2W0
#pragma unroll 1
    for (int c = 0; c < 4; c++) {
        if (c < 3) {
            unsigned wb = ((c + 1) & 1) ? N2W1 : N2W0;
            unsigned ab = ((c + 1) & 1) ? N2A1 : N2A0;
            load_w64(sbase + wb, g_nW1f + (c + 1) * 64 * DD, tid);
            loadA(c + 1, ab);
        } else {
            load_w64(sbase + N2W0, g_nW2f, tid);
        }
        cp_commit();
        unsigned wb = (c & 1) ? N2W1 : N2W0;
        unsigned ab = (c & 1) ? N2A1 : N2A0;
        mma_chunk64_e(acc, sbase + ab, 72, 0, sbase + wb, wm, wn, lane);
        if (c < 3) { cp_wait0(); __syncthreads(); }
    }

    // hidden -> dedicated N2H; W2c0 drains under it
    hidden_store_e(acc, (__half*)(smc + N2H), b1S, wm, wn, lane);
    cp_wait0();
    __syncthreads();

    // prefetch W2c1 into dead N2W1, overlapped with GEMM2 c0
    load_w64(sbase + N2W1, g_nW2f + 64 * DD, tid);
    cp_commit();
    mma_chunk64_e(acc, sbase + N2H, 136, 0, sbase + N2W0, wm, wn, lane);
    cp_wait0();
    __syncthreads();
    mma_chunk64_e(acc, sbase + N2H, 136, 64, sbase + N2W1, wm, wn, lane);
    __syncthreads();

    out_store_e(acc, Hs, b2S, wm, wn, lane);
    __syncthreads();
    stats_rows64(Hs, muS, invS, wid, lane);
    __syncthreads();

    // ---- LN + residual + PairNorm partials ----
    const int c4 = 4 * lane;
    float4 g4 = *(const float4*)(gmaS + c4);
    float4 t4 = *(const float4*)(btaS + c4);
    float4 cs = make_float4(0.f, 0.f, 0.f, 0.f);
    float sq_acc = 0.f;
#pragma unroll 1
    for (int j = 0; j < 8; j++) {
        int r = wid * 8 + j;
        if (r >= Nloc) continue;
        size_t gn = (size_t)(nb + r);
        float mu = muS[r], inv = invS[r];
        float4 v = *(const float4*)(Hs + r * 132 + c4);
        float4 xv = *(const float4*)(x + gn * DD + c4);
        float4 xp;
        xp.x = xv.x + (v.x - mu) * inv * g4.x + t4.x;
        xp.y = xv.y + (v.y - mu) * inv * g4.y + t4.y;
        xp.z = xv.z + (v.z - mu) * inv * g4.z + t4.z;
        xp.w = xv.w + (v.w - mu) * inv * g4.w + t4.w;
        *(float4*)(xpre + gn * DD + c4) = xp;
        cs.x += xp.x; cs.y += xp.y; cs.z += xp.z; cs.w += xp.w;
        sq_acc += xp.x * xp.x + xp.y * xp.y + xp.z * xp.z + xp.w * xp.w;
    }
    atomicAdd(&csum_s[c4 + 0], cs.x);
    atomicAdd(&csum_s[c4 + 1], cs.y);
    atomicAdd(&csum_s[c4 + 2], cs.z);
    atomicAdd(&csum_s[c4 + 3], cs.w);
#pragma unroll
    for (int o = 16; o > 0; o >>= 1) sq_acc += __shfl_xor_sync(0xffffffffu, sq_acc, o);
    if (lane == 0) atomicAdd(&csum_s[128], sq_acc);
    __syncthreads();
    if (tid < 128)       atomicAdd(&g_colsum[tid], csum_s[tid]);
    else if (tid == 128) atomicAdd(&g_sumsq[0],    csum_s[128]);
}

// ---------------------------------------------------------------------------
__global__ void rms_kernel(int Nn)
{
    __shared__ float red[128];
    int c = threadIdx.x;
    float m = g_colsum[c] / (float)Nn;
    g_mean[c] = m;
    red[c] = m * m;
    __syncthreads();
    for (int o = 64; o > 0; o >>= 1) {
        if (c < o) red[c] += red[c + o];
        __syncthreads();
    }
    if (c == 0) {
        float ssc = g_sumsq[0] - (float)Nn * red[0];
        float rms = sqrtf(ssc / (float)Nn) + 1e-8f;
        g_invrms[0] = 1.0f / rms;
    }
}

__global__ void finalize_kernel(float* __restrict__ xout, int n4)
{
    int base = blockIdx.x * (blockDim.x * 4) + threadIdx.x;
    float inv = g_invrms[0];
#pragma unroll
    for (int k = 0; k < 4; k++) {
        int i = base + k * 256;
        if (i < n4) {
            float4 v = ((const float4*)xout)[i];
            int c = (i * 4) & 127;
            v.x = (v.x - g_mean[c])     * inv;
            v.y = (v.y - g_mean[c + 1]) * inv;
            v.z = (v.z - g_mean[c + 2]) * inv;
            v.w = (v.w - g_mean[c + 3]) * inv;
            ((float4*)xout)[i] = v;
        }
    }
}

// ---------------------------------------------------------------------------
extern "C" void kernel_launch(void* const* d_in, const int* in_sizes, int n_in,
                              void* d_out, int out_size)
{
    const float* x   = (const float*)d_in[0];
    const float* ea  = (const float*)d_in[1];
    const int*   ei  = (const int*)d_in[2];      // int32 (JAX x64 disabled)
    const float* eW1 = (const float*)d_in[3];
    const float* eb1 = (const float*)d_in[4];
    const float* eW2 = (const float*)d_in[5];
    const float* eb2 = (const float*)d_in[6];
    const float* eg  = (const float*)d_in[7];
    const float* ebt = (const float*)d_in[8];
    const float* nW1 = (const float*)d_in[9];
    const float* nb1 = (const float*)d_in[10];
    const float* nW2 = (const float*)d_in[11];
    const float* nb2 = (const float*)d_in[12];
    const float* ng  = (const float*)d_in[13];
    const float* nbt = (const float*)d_in[14];

    const int Nn = in_sizes[0] / DD;
    const int E  = in_sizes[1] / DD;

    float* xout = (float*)d_out;
    float* eout = xout + (size_t)Nn * DD;

    cudaFuncSetAttribute(edge_kernel,  cudaFuncAttributeMaxDynamicSharedMemorySize, ESMEM_BYTES);
    cudaFuncSetAttribute(node_kernel,  cudaFuncAttributeMaxDynamicSharedMemorySize, NSMEM_BYTES);
    cudaFuncSetAttribute(precompute_P, cudaFuncAttributeMaxDynamicSharedMemorySize, PSMEM_BYTES);

    void *aggp, *csp, *sqp;
    cudaGetSymbolAddress(&aggp, g_aggh);
    cudaGetSymbolAddress(&csp,  g_colsum);
    cudaGetSymbolAddress(&sqp,  g_sumsq);

    cudaMemsetAsync(aggp, 0, (size_t)Nn * DD * sizeof(__half));
    cudaMemsetAsync(csp,  0, DD * sizeof(float));
    cudaMemsetAsync(sqp,  0, sizeof(float));

    {
        int n4x  = Nn * DD / 4;
        int wtot = 7 * DD * DD / 4;
        prep_all<<<(n4x + wtot + 255) / 256, 256>>>(x, n4x, eW1, eW2, nW1, nW2);
    }

    const int pblocks = (Nn + TB - 1) / TB;
    precompute_P<<<pblocks, NTHR, PSMEM_BYTES>>>(Nn);

    const int eblocks = (E + TB - 1) / TB;
    edge_kernel<<<eblocks, NTHR, ESMEM_BYTES>>>(ea, ei, eb1, eb2, eg, ebt, eout, E);

    const int nblocks = (Nn + TB - 1) / TB;
    node_kernel<<<nblocks, NTHR, NSMEM_BYTES>>>(x, nb1, nb2, ng, nbt, xout, Nn);

    rms_kernel<<<1, 128>>>(Nn);

    const int n4 = Nn * DD / 4;
    finalize_kernel<<<(n4 + 1023) / 1024, 256>>>(xout, n4);
}